// round 8
// baseline (speedup 1.0000x reference)
#include <cuda_runtime.h>
#include <math.h>

// Problem constants
#define PB   32      // batch
#define PS   1024    // seq len
#define PD   3       // dsize
#define PNF  512     // n fourier samples
#define PNS  64      // noise size
#define PH   100     // hidden
#define PFS  256     // fourier feature size
#define PCH  16      // chunks along S
#define PLS  64      // S per chunk  (PS / PCH)
#define PNPT 2       // n per thread in k1 (256 per half-block / 128 threads)
#define TN   4       // n rows per k_feat block

#define MU_C   10.0f
#define LOG2C  (-3947.8417604357434f)   // -MU*T*(2*pi)^(D-1) = -100*(2pi)^2

// ---------------- scratch (no allocations allowed) ----------------
__device__ float4 g_womg4[PNF];                // (w0,w1,w2,0) per n
__device__ float  g_sumC[PB * PCH * PNF];      // per-chunk sums  (1 MB, L2-resident)
__device__ float  g_sumS[PB * PCH * PNF];
__device__ float  g_local0[PB * PS];           // within-chunk part, n in [0,256)
__device__ float  g_local1[PB * PS];           // within-chunk part, n in [256,512)

// ================= k_feat: tiled MLP -> Womg  (TN n-rows per block) =========
// Round-6 profile: old k_feat was latency-bound (19.3us, occ 20%, issue 11%):
// 100-deep dependent FMA chains with per-iter global loads. New: W1 staged in
// smem, layer-2 thread owns one f column and accumulates TN independent
// n-rows per coalesced W2 load (ILP=TN).
__global__ __launch_bounds__(256) void k_feat(
    const float* __restrict__ noise, const float* __restrict__ W1,
    const float* __restrict__ b1,    const float* __restrict__ W2,
    const float* __restrict__ b2,    const float* __restrict__ W) {
    __shared__ float sh_noise[TN][PNS];      // 4*64   = 1 KB
    __shared__ float sh_W1[PNS * PH];        // 6400   = 25.6 KB
    __shared__ float sh_hid[TN][PH];         // 4*100  = 1.6 KB
    __shared__ float sh_red[8][TN * 3];      // warp partials for womg

    int n0 = blockIdx.x * TN;
    int tid = threadIdx.x;
    int lane = tid & 31, w = tid >> 5;

    // stage noise tile (coalesced) and W1 (coalesced)
    {
        int i = tid >> 6, k = tid & 63;               // 256 threads = 4*64
        sh_noise[i][k] = noise[(n0 + i) * PNS + k];
    }
    for (int j = tid; j < PNS * PH; j += 256) sh_W1[j] = W1[j];
    __syncthreads();

    // layer 1: hidden[i][h] = tanh(noise_i . W1[:,h] + b1[h]); 400 outputs
    for (int o = tid; o < TN * PH; o += 256) {
        int i = o / PH, hh = o % PH;
        float acc = b1[hh];
        #pragma unroll 8
        for (int k = 0; k < PNS; k++)
            acc = fmaf(sh_noise[i][k], sh_W1[k * PH + hh], acc);
        sh_hid[i][hh] = tanhf(acc);
    }
    __syncthreads();

    // layer 2: thread owns f = tid; 4 independent n accumulators per W2 load
    int f = tid;                                   // PFS == 256 == blockDim
    float acc0 = b2[f], acc1 = acc0, acc2 = acc0, acc3 = acc0;
    #pragma unroll 5
    for (int k = 0; k < PH; k++) {
        float w2 = W2[k * PFS + f];                // coalesced LDG
        acc0 = fmaf(sh_hid[0][k], w2, acc0);
        acc1 = fmaf(sh_hid[1][k], w2, acc1);
        acc2 = fmaf(sh_hid[2][k], w2, acc2);
        acc3 = fmaf(sh_hid[3][k], w2, acc3);
    }
    float fv0 = tanhf(acc0), fv1 = tanhf(acc1), fv2 = tanhf(acc2), fv3 = tanhf(acc3);

    // layer 3: womg[n] = sum_f fv[n] * W[f,:]; 12 warp-butterfly reductions
    float w0 = W[f * PD + 0], w1 = W[f * PD + 1], w2c = W[f * PD + 2];
    float p[TN * 3] = { fv0 * w0, fv0 * w1, fv0 * w2c,
                        fv1 * w0, fv1 * w1, fv1 * w2c,
                        fv2 * w0, fv2 * w1, fv2 * w2c,
                        fv3 * w0, fv3 * w1, fv3 * w2c };
    #pragma unroll
    for (int d = 16; d >= 1; d >>= 1) {
        #pragma unroll
        for (int j = 0; j < TN * 3; j++)
            p[j] += __shfl_xor_sync(0xffffffffu, p[j], d);
    }
    if (lane == 0) {
        #pragma unroll
        for (int j = 0; j < TN * 3; j++) sh_red[w][j] = p[j];
    }
    __syncthreads();
    if (tid < TN) {
        float r0 = 0.f, r1 = 0.f, r2 = 0.f;
        #pragma unroll
        for (int ww = 0; ww < 8; ww++) {
            r0 += sh_red[ww][tid * 3 + 0];
            r1 += sh_red[ww][tid * 3 + 1];
            r2 += sh_red[ww][tid * 3 + 2];
        }
        g_womg4[n0 + tid] = make_float4(r0, r1, r2, 0.f);
    }
}

// ================= k1: within-chunk scan + chunk sums =======================
// grid = B*PCH*2 blocks (n-range split in half for occupancy), 128 threads,
// 2 fourier components per thread. Per-s partial -> padded shared (single STS,
// no in-loop SHFL chain), two-stage bulk column-reduce at the end.
__global__ __launch_bounds__(128) void k1(const float* __restrict__ X) {
    __shared__ float sx[PLS * PD];        // X chunk (192 floats)
    __shared__ float part[128][PLS + 1];  // [thread][s], padded (33 KB)
    __shared__ float half1[PLS];          // upper-half partial per s

    int blk = blockIdx.x;
    int h = blk & 1;                      // n half: 0 -> [0,256), 1 -> [256,512)
    int bc = blk >> 1;
    int b = bc / PCH, c = bc % PCH;
    int tid = threadIdx.x;

    const float* xp = X + (size_t)(b * PS + c * PLS) * PD;
    for (int i = tid; i < PLS * PD; i += 128) sx[i] = xp[i];

    float4 wv[PNPT];
    #pragma unroll
    for (int j = 0; j < PNPT; j++) wv[j] = g_womg4[h * 256 + j * 128 + tid];
    __syncthreads();

    float runC[PNPT] = {0.f, 0.f};
    float runS[PNPT] = {0.f, 0.f};

    #pragma unroll 4
    for (int ls = 0; ls < PLS; ls++) {
        float x0 = sx[ls * 3 + 0];
        float x1 = sx[ls * 3 + 1];
        float x2 = sx[ls * 3 + 2];
        float contrib = 0.f;
        #pragma unroll
        for (int j = 0; j < PNPT; j++) {
            float th = fmaf(x2, wv[j].z, fmaf(x1, wv[j].y, x0 * wv[j].x));
            float sn, cs;
            __sincosf(th, &sn, &cs);
            contrib = fmaf(cs, runC[j], contrib);
            contrib = fmaf(sn, runS[j], contrib);
            runC[j] += cs; runS[j] += sn;
        }
        part[tid][ls] = contrib;          // single STS, no dependency chain
    }

    int base = (b * PCH + c) * PNF + h * 256;
    #pragma unroll
    for (int j = 0; j < PNPT; j++) {
        g_sumC[base + j * 128 + tid] = runC[j];
        g_sumS[base + j * 128 + tid] = runS[j];
    }
    __syncthreads();

    // two-stage column reduce using all 128 threads
    {
        int col = tid & (PLS - 1);
        int r0 = (tid < PLS) ? 0 : 64;
        float t = 0.f;
        #pragma unroll 8
        for (int i = 0; i < 64; i++) t += part[r0 + i][col];
        if (tid < PLS) part[0][col] = t;
        else           half1[col]   = t;
    }
    __syncthreads();
    if (tid < PLS) {
        float* dst = h ? g_local1 : g_local0;
        dst[b * PS + c * PLS + tid] = part[0][tid] + half1[tid];
    }
}

// ================= k3: cross-chunk term + finalize lam / loglik =============
// grid = B*PCH blocks, 256 threads, s handled by 4 threads (n split 4 ways).
// Phase trick: offC*cos(th) + offS*sin(th) = A*cos(th - phi) -> 1 MUFU/iter.
__global__ __launch_bounds__(256) void k3(const float* __restrict__ X,
                                          const float* __restrict__ alpha,
                                          float* __restrict__ out) {
    __shared__ float4 swo[PNF];    // (w0,w1,w2,A)
    __shared__ float  sphi[PNF];   // phi
    __shared__ float  red[3][PLS]; // partials from n-splits 1..3

    int blk = blockIdx.x;
    int b = blk / PCH, c = blk % PCH;
    int tid = threadIdx.x;

    for (int n = tid; n < PNF; n += 256) {
        float oc = 0.f, os = 0.f;
        for (int cp = 0; cp < c; cp++) {
            int idx = (b * PCH + cp) * PNF + n;
            oc += g_sumC[idx];
            os += g_sumS[idx];
        }
        float4 v = g_womg4[n];
        v.w = sqrtf(fmaf(oc, oc, os * os));      // A
        swo[n] = v;
        sphi[n] = atan2f(os, oc);                // phi (0 when c == 0)
    }

    int sid = tid & (PLS - 1);       // s within chunk
    int p   = tid >> 6;              // n-split 0..3
    int s = c * PLS + sid;
    const float* xp = X + (size_t)(b * PS + s) * PD;
    float x0 = __ldg(xp + 0), x1 = __ldg(xp + 1), x2 = __ldg(xp + 2);
    __syncthreads();

    float acc = 0.f;
    int n0 = p * (PNF / 4);
    #pragma unroll 8
    for (int k = 0; k < PNF / 4; k++) {
        int n = n0 + k;
        float4 v = swo[n];                 // LDS.128 broadcast
        float ph = sphi[n];                // LDS.32 broadcast
        float th = fmaf(x2, v.z, fmaf(x1, v.y, x0 * v.x)) - ph;
        acc = fmaf(v.w, __cosf(th), acc);  // A * cos(th - phi)
    }
    if (p > 0) red[p - 1][sid] = acc;
    __syncthreads();

    if (p == 0) {
        float total = acc + red[0][sid] + red[1][sid] + red[2][sid]
                    + g_local0[b * PS + s] + g_local1[b * PS + s];
        float ksum = total * (1.0f / PNF);
        float lam = fmaf(alpha[0], ksum, MU_C);
        out[b * PS + s] = lam;                                   // lam [B,S]
        float ll = (x0 > 0.f) ? __logf(lam) : 0.f;
        out[PB * PS + b * (PS + 1) + s] = ll + LOG2C;            // loglik [B,S+1]
        if (c == 0 && sid == 0)
            out[PB * PS + b * (PS + 1) + PS] = LOG2C;            // loglik[b,S] tail
    }
}

// ---------------- launcher: bind inputs by unique element count ------------
extern "C" void kernel_launch(void* const* d_in, const int* in_sizes, int n_in,
                              void* d_out, int out_size) {
    const float *X = 0, *noise = 0, *W1 = 0, *b1 = 0, *W2 = 0, *b2 = 0,
                *W = 0, *alpha = 0;
    for (int i = 0; i < n_in; i++) {
        const float* p = (const float*)d_in[i];
        switch (in_sizes[i]) {
            case PB * PS * PD:   X     = p; break;   // 98304
            case PNF * PNS:      noise = p; break;   // 32768
            case PNS * PH:       W1    = p; break;   // 6400
            case PH:             b1    = p; break;   // 100
            case PH * PFS:       W2    = p; break;   // 25600
            case PFS:            b2    = p; break;   // 256
            case PFS * PD:       W     = p; break;   // 768
            case 1:              alpha = p; break;   // 1
            default: break;
        }
    }
    float* out = (float*)d_out;

    k_feat<<<PNF / TN, 256>>>(noise, W1, b1, W2, b2, W);
    k1    <<<PB * PCH * 2, 128>>>(X);
    k3    <<<PB * PCH, 256>>>(X, alpha, out);
}

// round 17
// speedup vs baseline: 1.0513x; 1.0513x over previous
#include <cuda_runtime.h>
#include <math.h>

// Problem constants
#define PB   32      // batch
#define PS   1024    // seq len
#define PD   3       // dsize
#define PNF  512     // n fourier samples
#define PNS  64      // noise size
#define PH   100     // hidden
#define PFS  256     // fourier feature size
#define PCH  16      // chunks along S
#define PLS  64      // S per chunk  (PS / PCH)
#define PNPT 2       // n per thread in k1 (256 per half-block / 128 threads)
#define TN   4       // n rows per k_feat block
#define KG   4       // k-groups in k_feat layer 2 (block = KG*256 threads)
#define KPG  25      // k per group (PH / KG)

#define MU_C   10.0f
#define LOG2C  (-3947.8417604357434f)   // -MU*T*(2*pi)^(D-1) = -100*(2pi)^2

// ---------------- scratch (no allocations allowed) ----------------
__device__ float4 g_womg4[PNF];                // (w0,w1,w2,0) per n
__device__ float  g_sumC[PB * PCH * PNF];      // per-chunk sums  (1 MB, L2-resident)
__device__ float  g_sumS[PB * PCH * PNF];
__device__ float  g_local0[PB * PS];           // within-chunk part, n in [0,256)
__device__ float  g_local1[PB * PS];           // within-chunk part, n in [256,512)

// ================= k_feat: tiled MLP -> Womg  (TN n-rows per block) =========
// R6/R8 profiles: 19.3/19.8us, occ 12-20%, issue ~11%, pipes <3% -> per-block
// serial chain of ~100 L2-latency W2 loads, 8 warps/SM. Two fixes combined:
//  (a) explicit 8-wide LDG prefetch (ILP within thread)
//  (b) layer-2 k-dimension split over KG=4 thread groups (1024-thread block,
//      32 warps/SM, serial chain 100 -> 25 loads), partials combined in smem.
__global__ __launch_bounds__(KG * 256) void k_feat(
    const float* __restrict__ noise, const float* __restrict__ W1,
    const float* __restrict__ b1,    const float* __restrict__ W2,
    const float* __restrict__ b2,    const float* __restrict__ W) {
    __shared__ float sh_noise[TN][PNS];          // 1 KB
    __shared__ float sh_W1[PNS * PH];            // 25.6 KB
    __shared__ float sh_hid[TN][PH];             // 1.6 KB
    __shared__ float sh_part[KG - 1][PFS][TN];   // 12 KB layer-2 partials
    __shared__ float sh_red[8][TN * 3];          // warp partials for womg

    int n0 = blockIdx.x * TN;
    int tid = threadIdx.x;
    int f = tid & (PFS - 1);                     // 0..255
    int g = tid >> 8;                            // k-group 0..3
    int lane = tid & 31, w = tid >> 5;           // w: 0..31

    // stage noise tile (first 256 threads) and W1 via float4 (coalesced)
    if (tid < 256) {
        int i = tid >> 6, k = tid & 63;
        sh_noise[i][k] = noise[(n0 + i) * PNS + k];
    }
    {
        const float4* W14 = (const float4*)W1;   // 6400 floats = 1600 vec4
        float4* sW14 = (float4*)sh_W1;
        if (tid < 1024) sW14[tid] = W14[tid];
        if (tid < 1600 - 1024) sW14[tid + 1024] = W14[tid + 1024];
    }
    __syncthreads();

    // layer 1: hidden[i][h] = tanh(noise_i . W1[:,h] + b1[h]); 400 outputs
    if (tid < TN * PH) {
        int i = tid / PH, hh = tid % PH;
        float acc = b1[hh];
        #pragma unroll
        for (int k0 = 0; k0 < PNS; k0 += 8) {
            float wb[8];
            #pragma unroll
            for (int j = 0; j < 8; j++) wb[j] = sh_W1[(k0 + j) * PH + hh];
            #pragma unroll
            for (int j = 0; j < 8; j++)
                acc = fmaf(sh_noise[i][k0 + j], wb[j], acc);
        }
        sh_hid[i][hh] = tanhf(acc);
    }
    __syncthreads();

    // layer 2: group g covers k in [g*25, g*25+25), 8-wide LDG prefetch,
    // 4 independent n accumulators per load. 25 = 3*8 + 1.
    float acc0, acc1, acc2, acc3;
    acc0 = (g == 0) ? b2[f] : 0.f;
    acc1 = acc0; acc2 = acc0; acc3 = acc0;
    const float* w2p = W2 + f;
    int kb = g * KPG;
    #pragma unroll
    for (int k0 = 0; k0 < 24; k0 += 8) {
        float buf[8];
        #pragma unroll
        for (int j = 0; j < 8; j++) buf[j] = w2p[(kb + k0 + j) * PFS];  // 8 indep LDG
        #pragma unroll
        for (int j = 0; j < 8; j++) {
            int k = kb + k0 + j;
            acc0 = fmaf(sh_hid[0][k], buf[j], acc0);
            acc1 = fmaf(sh_hid[1][k], buf[j], acc1);
            acc2 = fmaf(sh_hid[2][k], buf[j], acc2);
            acc3 = fmaf(sh_hid[3][k], buf[j], acc3);
        }
    }
    {   // tail k = kb + 24
        float w2v = w2p[(kb + 24) * PFS];
        int k = kb + 24;
        acc0 = fmaf(sh_hid[0][k], w2v, acc0);
        acc1 = fmaf(sh_hid[1][k], w2v, acc1);
        acc2 = fmaf(sh_hid[2][k], w2v, acc2);
        acc3 = fmaf(sh_hid[3][k], w2v, acc3);
    }
    if (g > 0) {
        sh_part[g - 1][f][0] = acc0;
        sh_part[g - 1][f][1] = acc1;
        sh_part[g - 1][f][2] = acc2;
        sh_part[g - 1][f][3] = acc3;
    }
    __syncthreads();

    // group 0 combines partials, applies tanh, does layer-3 reduce
    if (g == 0) {
        #pragma unroll
        for (int q = 0; q < KG - 1; q++) {
            acc0 += sh_part[q][f][0];
            acc1 += sh_part[q][f][1];
            acc2 += sh_part[q][f][2];
            acc3 += sh_part[q][f][3];
        }
        float fv0 = tanhf(acc0), fv1 = tanhf(acc1), fv2 = tanhf(acc2), fv3 = tanhf(acc3);

        // layer 3: womg[n] = sum_f fv[n] * W[f,:]; 12 warp-butterfly reductions
        float w0 = W[f * PD + 0], w1 = W[f * PD + 1], w2c = W[f * PD + 2];
        float p[TN * 3] = { fv0 * w0, fv0 * w1, fv0 * w2c,
                            fv1 * w0, fv1 * w1, fv1 * w2c,
                            fv2 * w0, fv2 * w1, fv2 * w2c,
                            fv3 * w0, fv3 * w1, fv3 * w2c };
        #pragma unroll
        for (int d = 16; d >= 1; d >>= 1) {
            #pragma unroll
            for (int j = 0; j < TN * 3; j++)
                p[j] += __shfl_xor_sync(0xffffffffu, p[j], d);
        }
        if (lane == 0) {
            #pragma unroll
            for (int j = 0; j < TN * 3; j++) sh_red[w][j] = p[j];  // w in 0..7
        }
    }
    __syncthreads();
    if (tid < TN) {
        float r0 = 0.f, r1 = 0.f, r2 = 0.f;
        #pragma unroll
        for (int ww = 0; ww < 8; ww++) {
            r0 += sh_red[ww][tid * 3 + 0];
            r1 += sh_red[ww][tid * 3 + 1];
            r2 += sh_red[ww][tid * 3 + 2];
        }
        g_womg4[n0 + tid] = make_float4(r0, r1, r2, 0.f);
    }
}

// ================= k1: within-chunk scan + chunk sums =======================
// grid = B*PCH*2 blocks (n-range split in half for occupancy), 128 threads,
// 2 fourier components per thread. Per-s partial -> padded shared (single STS,
// no in-loop SHFL chain), two-stage bulk column-reduce at the end.
__global__ __launch_bounds__(128) void k1(const float* __restrict__ X) {
    __shared__ float sx[PLS * PD];        // X chunk (192 floats)
    __shared__ float part[128][PLS + 1];  // [thread][s], padded (33 KB)
    __shared__ float half1[PLS];          // upper-half partial per s

    int blk = blockIdx.x;
    int h = blk & 1;                      // n half: 0 -> [0,256), 1 -> [256,512)
    int bc = blk >> 1;
    int b = bc / PCH, c = bc % PCH;
    int tid = threadIdx.x;

    const float* xp = X + (size_t)(b * PS + c * PLS) * PD;
    for (int i = tid; i < PLS * PD; i += 128) sx[i] = xp[i];

    float4 wv[PNPT];
    #pragma unroll
    for (int j = 0; j < PNPT; j++) wv[j] = g_womg4[h * 256 + j * 128 + tid];
    __syncthreads();

    float runC[PNPT] = {0.f, 0.f};
    float runS[PNPT] = {0.f, 0.f};

    #pragma unroll 4
    for (int ls = 0; ls < PLS; ls++) {
        float x0 = sx[ls * 3 + 0];
        float x1 = sx[ls * 3 + 1];
        float x2 = sx[ls * 3 + 2];
        float contrib = 0.f;
        #pragma unroll
        for (int j = 0; j < PNPT; j++) {
            float th = fmaf(x2, wv[j].z, fmaf(x1, wv[j].y, x0 * wv[j].x));
            float sn, cs;
            __sincosf(th, &sn, &cs);
            contrib = fmaf(cs, runC[j], contrib);
            contrib = fmaf(sn, runS[j], contrib);
            runC[j] += cs; runS[j] += sn;
        }
        part[tid][ls] = contrib;          // single STS, no dependency chain
    }

    int base = (b * PCH + c) * PNF + h * 256;
    #pragma unroll
    for (int j = 0; j < PNPT; j++) {
        g_sumC[base + j * 128 + tid] = runC[j];
        g_sumS[base + j * 128 + tid] = runS[j];
    }
    __syncthreads();

    // two-stage column reduce using all 128 threads
    {
        int col = tid & (PLS - 1);
        int r0 = (tid < PLS) ? 0 : 64;
        float t = 0.f;
        #pragma unroll 8
        for (int i = 0; i < 64; i++) t += part[r0 + i][col];
        if (tid < PLS) part[0][col] = t;
        else           half1[col]   = t;
    }
    __syncthreads();
    if (tid < PLS) {
        float* dst = h ? g_local1 : g_local0;
        dst[b * PS + c * PLS + tid] = part[0][tid] + half1[tid];
    }
}

// ================= k3: cross-chunk term + finalize lam / loglik =============
// grid = B*PCH blocks, 256 threads, s handled by 4 threads (n split 4 ways).
// Phase trick: offC*cos(th) + offS*sin(th) = A*cos(th - phi) -> 1 MUFU/iter.
__global__ __launch_bounds__(256) void k3(const float* __restrict__ X,
                                          const float* __restrict__ alpha,
                                          float* __restrict__ out) {
    __shared__ float4 swo[PNF];    // (w0,w1,w2,A)
    __shared__ float  sphi[PNF];   // phi
    __shared__ float  red[3][PLS]; // partials from n-splits 1..3

    int blk = blockIdx.x;
    int b = blk / PCH, c = blk % PCH;
    int tid = threadIdx.x;

    for (int n = tid; n < PNF; n += 256) {
        float oc = 0.f, os = 0.f;
        for (int cp = 0; cp < c; cp++) {
            int idx = (b * PCH + cp) * PNF + n;
            oc += g_sumC[idx];
            os += g_sumS[idx];
        }
        float4 v = g_womg4[n];
        v.w = sqrtf(fmaf(oc, oc, os * os));      // A
        swo[n] = v;
        sphi[n] = atan2f(os, oc);                // phi (0 when c == 0)
    }

    int sid = tid & (PLS - 1);       // s within chunk
    int p   = tid >> 6;              // n-split 0..3
    int s = c * PLS + sid;
    const float* xp = X + (size_t)(b * PS + s) * PD;
    float x0 = __ldg(xp + 0), x1 = __ldg(xp + 1), x2 = __ldg(xp + 2);
    __syncthreads();

    float acc = 0.f;
    int n0 = p * (PNF / 4);
    #pragma unroll 8
    for (int k = 0; k < PNF / 4; k++) {
        int n = n0 + k;
        float4 v = swo[n];                 // LDS.128 broadcast
        float ph = sphi[n];                // LDS.32 broadcast
        float th = fmaf(x2, v.z, fmaf(x1, v.y, x0 * v.x)) - ph;
        acc = fmaf(v.w, __cosf(th), acc);  // A * cos(th - phi)
    }
    if (p > 0) red[p - 1][sid] = acc;
    __syncthreads();

    if (p == 0) {
        float total = acc + red[0][sid] + red[1][sid] + red[2][sid]
                    + g_local0[b * PS + s] + g_local1[b * PS + s];
        float ksum = total * (1.0f / PNF);
        float lam = fmaf(alpha[0], ksum, MU_C);
        out[b * PS + s] = lam;                                   // lam [B,S]
        float ll = (x0 > 0.f) ? __logf(lam) : 0.f;
        out[PB * PS + b * (PS + 1) + s] = ll + LOG2C;            // loglik [B,S+1]
        if (c == 0 && sid == 0)
            out[PB * PS + b * (PS + 1) + PS] = LOG2C;            // loglik[b,S] tail
    }
}

// ---------------- launcher: bind inputs by unique element count ------------
extern "C" void kernel_launch(void* const* d_in, const int* in_sizes, int n_in,
                              void* d_out, int out_size) {
    const float *X = 0, *noise = 0, *W1 = 0, *b1 = 0, *W2 = 0, *b2 = 0,
                *W = 0, *alpha = 0;
    for (int i = 0; i < n_in; i++) {
        const float* p = (const float*)d_in[i];
        switch (in_sizes[i]) {
            case PB * PS * PD:   X     = p; break;   // 98304
            case PNF * PNS:      noise = p; break;   // 32768
            case PNS * PH:       W1    = p; break;   // 6400
            case PH:             b1    = p; break;   // 100
            case PH * PFS:       W2    = p; break;   // 25600
            case PFS:            b2    = p; break;   // 256
            case PFS * PD:       W     = p; break;   // 768
            case 1:              alpha = p; break;   // 1
            default: break;
        }
    }
    float* out = (float*)d_out;

    k_feat<<<PNF / TN, KG * 256>>>(noise, W1, b1, W2, b2, W);
    k1    <<<PB * PCH * 2, 128>>>(X);
    k3    <<<PB * PCH, 256>>>(X, alpha, out);
}